// round 7
// baseline (speedup 1.0000x reference)
#include <cuda_runtime.h>
#include <cstdint>

// out[B,10] = x[B,64] @ W[64,10], fp32, B = 2,097,152.
// R6: R5 had 1 warp/SMSP (occ 6.3%) -> issue 16%, DRAM 51%. Fix: small tiles
// (256 rows), 4 fully-prefetched 20KB k-stage buffers (no reuse -> all cp.async
// issued at block start), 83KB smem/CTA -> 2 CTAs/SM = 4 warps/SMSP.

#define BATCH     2097152
#define IN_DIM    64
#define OUT_DIM   10
#define BLOCK     256
#define TILE_ROWS 256
#define KSTAGES   4                           // 4 x 16 floats = 64 k
#define ROW_STRIDE 80                         // 64B data + 16B pad (gcd(5,8)=1)
#define STAGE_BYTES (TILE_ROWS * ROW_STRIDE)  // 20480
#define W_OFF     (KSTAGES * STAGE_BYTES)     // 81920
#define SMEM_TOTAL (W_OFF + IN_DIM * 48)      // 84992 bytes -> 2 CTAs/SM

__device__ __forceinline__ void ffma2(uint64_t& d, uint64_t a, uint64_t b) {
    asm volatile("fma.rn.f32x2 %0, %1, %2, %0;" : "+l"(d) : "l"(a), "l"(b));
}

__device__ __forceinline__ uint64_t dup2(float v) {
    uint64_t d;
    asm("mov.b64 %0, {%1, %1};" : "=l"(d) : "f"(v));
    return d;
}

__global__ void __launch_bounds__(BLOCK) neat_matmul_kernel(
    const float* __restrict__ x,
    const float* __restrict__ W,
    float* __restrict__ out)
{
    extern __shared__ __align__(128) unsigned char smem[];
    const int tid = threadIdx.x;
    const size_t tileBase = (size_t)blockIdx.x * TILE_ROWS;
    const char* xbase = reinterpret_cast<const char*>(x) + tileBase * (IN_DIM * 4);

    // ---- Issue ALL x prefetches first (4 groups, one per k-stage). ----
    // Stage s = rows 0..255, bytes [s*64, s*64+64). Per stage: 4 cp.async/thread.
    // g = tid + i*256: lanes 4l..4l+3 fetch 64B contiguous of row (g>>2).
#pragma unroll
    for (int s = 0; s < KSTAGES; ++s) {
        unsigned dstbase =
            (unsigned)__cvta_generic_to_shared(smem + (size_t)s * STAGE_BYTES);
#pragma unroll
        for (int i = 0; i < 4; ++i) {
            int g = tid + i * BLOCK;          // 0..1023
            int r = g >> 2, c = g & 3;
            const char* src = xbase + r * 256 + s * 64 + c * 16;
            unsigned dst = dstbase + r * ROW_STRIDE + c * 16;
            asm volatile("cp.async.cg.shared.global [%0], [%1], 16;"
                         :: "r"(dst), "l"(src) : "memory");
        }
        asm volatile("cp.async.commit_group;" ::: "memory");
    }

    // ---- Stage W (overlaps with x fetch): Ws[k][p] = (W[k][2p],W[k][2p+1]). ----
    {
        uint64_t* Ws = reinterpret_cast<uint64_t*>(smem + W_OFF);
        for (int t = tid; t < IN_DIM * 5; t += BLOCK) {
            int k = t / 5, p = t % 5;
            uint64_t v;
            asm("mov.b64 %0, {%1, %2};" : "=l"(v)
                : "f"(W[k * OUT_DIM + 2 * p]), "f"(W[k * OUT_DIM + 2 * p + 1]));
            Ws[k * 6 + p] = v;
        }
    }

    uint64_t acc[5];
#pragma unroll
    for (int p = 0; p < 5; ++p) acc[p] = 0ull;

    const uint64_t* Ws = reinterpret_cast<const uint64_t*>(smem + W_OFF);
    const unsigned char* myrow = smem + tid * ROW_STRIDE;

#pragma unroll
    for (int s = 0; s < KSTAGES; ++s) {
        // Drain groups in order: after stage s arrives, 3-s groups remain.
        if (s == 0)      asm volatile("cp.async.wait_group 3;" ::: "memory");
        else if (s == 1) asm volatile("cp.async.wait_group 2;" ::: "memory");
        else if (s == 2) asm volatile("cp.async.wait_group 1;" ::: "memory");
        else             asm volatile("cp.async.wait_group 0;" ::: "memory");
        __syncthreads();   // cross-thread visibility of this stage (and W on s=0)

        const unsigned char* buf = myrow + (size_t)s * STAGE_BYTES;

#pragma unroll
        for (int c = 0; c < 4; ++c) {
            // own row, 80B stride: lanes hit granule (5*lane+c)&7 -> conflict-free
            const float4 xv = *reinterpret_cast<const float4*>(buf + c * 16);
#pragma unroll
            for (int q = 0; q < 4; ++q) {
                const int k = s * 16 + c * 4 + q;
                const ulonglong2 w01 =
                    *reinterpret_cast<const ulonglong2*>(Ws + k * 6);
                const ulonglong2 w23 =
                    *reinterpret_cast<const ulonglong2*>(Ws + k * 6 + 2);
                const uint64_t w4 = Ws[k * 6 + 4];
                const float xk = (q == 0) ? xv.x : (q == 1) ? xv.y :
                                 (q == 2) ? xv.z : xv.w;
                const uint64_t xx = dup2(xk);
                ffma2(acc[0], xx, w01.x);
                ffma2(acc[1], xx, w01.y);
                ffma2(acc[2], xx, w23.x);
                ffma2(acc[3], xx, w23.y);
                ffma2(acc[4], xx, w4);
            }
        }
    }

    // acc pairs are (out[2p], out[2p+1]) -> 5 x STG.64 streaming, no reduce.
    unsigned long long* __restrict__ o =
        reinterpret_cast<unsigned long long*>(out + (tileBase + tid) * OUT_DIM);
#pragma unroll
    for (int p = 0; p < 5; ++p)
        __stcs(o + p, (unsigned long long)acc[p]);
}

extern "C" void kernel_launch(void* const* d_in, const int* in_sizes, int n_in,
                              void* d_out, int out_size) {
    const float* x = (const float*)d_in[0];  // [BATCH, 64]
    const float* W = (const float*)d_in[1];  // [64, 10] row-major
    float* out = (float*)d_out;              // [BATCH, 10]

    static int configured = 0;
    if (!configured) {
        cudaFuncSetAttribute(neat_matmul_kernel,
                             cudaFuncAttributeMaxDynamicSharedMemorySize,
                             SMEM_TOTAL);
        configured = 1;
    }

    const int grid = BATCH / TILE_ROWS;  // 8192, exact
    neat_matmul_kernel<<<grid, BLOCK, SMEM_TOTAL>>>(x, W, out);
}

// round 9
// speedup vs baseline: 1.1607x; 1.1607x over previous
#include <cuda_runtime.h>
#include <cstdint>

// out[B,10] = x[B,64] @ W[64,10], fp32, B = 2,097,152.
// R7: all smem variants plateaued at 45-51% DRAM (phase-structured stalls;
// W delivery loaded the L1/LSU path). Fix: W -> __constant__ (separate const
// port, warp-uniform ULDC), packed as k-pair u64 (W[2kk][j],W[2kk+1][j]) by a
// prep kernel so x float4 loads give matching (x[2kk],x[2kk+1]) pairs free.
// Main kernel: no smem, no barriers; RPT=2 + PF=4 register pipeline.

#define BATCH   2097152
#define IN_DIM  64
#define OUT_DIM 10
#define BLOCK   256
#define RPT     2
#define PF      4
#define NCHUNK  16                      // 16B chunks per 256B row
#define ROWS_PER_BLOCK (BLOCK * RPT)    // 512

__device__ unsigned long long Wstage[320];   // staging, written by prep kernel
__constant__ unsigned long long cW[320];     // cW[kk*10+j] = (W[2kk][j], W[2kk+1][j])

__global__ void prep_kernel(const float* __restrict__ W) {
    int t = threadIdx.x;                 // 0..319
    if (t < 320) {
        int kk = t / OUT_DIM, j = t % OUT_DIM;
        unsigned long long v;
        asm("mov.b64 %0, {%1, %2};" : "=l"(v)
            : "f"(W[(2 * kk) * OUT_DIM + j]),
              "f"(W[(2 * kk + 1) * OUT_DIM + j]));
        Wstage[t] = v;
    }
}

__device__ __forceinline__ void ffma2(uint64_t& d, uint64_t a, uint64_t b) {
    // packed 2xFP32 FMA: d = a*b + d
    asm volatile("fma.rn.f32x2 %0, %1, %2, %0;" : "+l"(d) : "l"(a), "l"(b));
}

__global__ void __launch_bounds__(BLOCK, 2) neat_matmul_kernel(
    const float* __restrict__ x,
    float* __restrict__ out)
{
    const int tid = threadIdx.x;
    const size_t base = (size_t)blockIdx.x * ROWS_PER_BLOCK + tid;

    // x row = 256B = 16 ulonglong2 chunks. ull2 load: .x=(x0,x1) .y=(x2,x3)
    // are ready-made f32x2 operands. Block-strided rows -> coalesced LDG.128.
    const ulonglong2* __restrict__ xb =
        reinterpret_cast<const ulonglong2*>(x) + base * NCHUNK;

    // acc[r][j] = (even-k partial, odd-k partial) for output j.
    uint64_t acc[RPT][OUT_DIM];
#pragma unroll
    for (int r = 0; r < RPT; ++r)
#pragma unroll
        for (int j = 0; j < OUT_DIM; ++j) acc[r][j] = 0ull;

    // Prime PF chunks per row.
    ulonglong2 buf[PF][RPT];
#pragma unroll
    for (int s = 0; s < PF; ++s)
#pragma unroll
        for (int r = 0; r < RPT; ++r)
            buf[s][r] = __ldcs(xb + (size_t)r * BLOCK * NCHUNK + s);

#pragma unroll
    for (int c = 0; c < NCHUNK; ++c) {
        ulonglong2 xv[RPT];
#pragma unroll
        for (int r = 0; r < RPT; ++r) xv[r] = buf[c % PF][r];

        if (c + PF < NCHUNK) {          // keep 3-4 chunks/row in flight always
#pragma unroll
            for (int r = 0; r < RPT; ++r)
                buf[c % PF][r] =
                    __ldcs(xb + (size_t)r * BLOCK * NCHUNK + c + PF);
        }

#pragma unroll
        for (int h = 0; h < 2; ++h) {   // two k-pairs per 16B chunk
            const int kk = 2 * c + h;
#pragma unroll
            for (int p = 0; p < 5; ++p) {
                // 16B const load: W-pairs for outputs (2p, 2p+1) of this kk.
                // Warp-uniform, compile-time offset -> const port, not LSU.
                const ulonglong2 w =
                    *reinterpret_cast<const ulonglong2*>(&cW[kk * OUT_DIM + 2 * p]);
#pragma unroll
                for (int r = 0; r < RPT; ++r) {
                    const uint64_t xp = (h == 0) ? xv[r].x : xv[r].y;
                    ffma2(acc[r][2 * p],     xp, w.x);
                    ffma2(acc[r][2 * p + 1], xp, w.y);
                }
            }
        }
    }

    // Horizontal add (even-k + odd-k halves), pack pairs, 5x STG.64 per row.
#pragma unroll
    for (int r = 0; r < RPT; ++r) {
        float s[OUT_DIM];
#pragma unroll
        for (int j = 0; j < OUT_DIM; ++j) {
            float lo, hi;
            asm("mov.b64 {%0, %1}, %2;" : "=f"(lo), "=f"(hi) : "l"(acc[r][j]));
            s[j] = lo + hi;
        }
        unsigned long long* __restrict__ o =
            reinterpret_cast<unsigned long long*>(
                out + (base + (size_t)r * BLOCK) * OUT_DIM);
#pragma unroll
        for (int p = 0; p < 5; ++p) {
            unsigned long long v;
            asm("mov.b64 %0, {%1, %2};" : "=l"(v) : "f"(s[2 * p]), "f"(s[2 * p + 1]));
            __stcs(o + p, v);
        }
    }
}

extern "C" void kernel_launch(void* const* d_in, const int* in_sizes, int n_in,
                              void* d_out, int out_size) {
    const float* x = (const float*)d_in[0];  // [BATCH, 64]
    const float* W = (const float*)d_in[1];  // [64, 10] row-major
    float* out = (float*)d_out;              // [BATCH, 10]

    // 1) pack W into k-pair u64s (device staging)
    prep_kernel<<<1, 320>>>(W);

    // 2) stage -> constant bank (D2D async memcpy: graph-capturable, no alloc)
    void* wsp = nullptr;
    cudaGetSymbolAddress(&wsp, Wstage);
    cudaMemcpyToSymbolAsync(cW, wsp, 320 * sizeof(unsigned long long), 0,
                            cudaMemcpyDeviceToDevice, 0);

    // 3) main streaming kernel
    const int grid = BATCH / ROWS_PER_BLOCK;   // 4096, exact
    neat_matmul_kernel<<<grid, BLOCK>>>(x, out);
}